// round 8
// baseline (speedup 1.0000x reference)
#include <cuda_runtime.h>

#define SEQ 4096
#define RPC 4                 // rows (warps) per CTA
#define TPB (RPC * 32)

__device__ __forceinline__ unsigned prmt(unsigned a, unsigned b, unsigned sel) {
    unsigned r;
    asm("prmt.b32 %0, %1, %2, %3;" : "=r"(r) : "r"(a), "r"(b), "r"(sel));
    return r;
}

// word-index swizzle: XOR bits[4:2] with bits[7:5]; keeps 16B groups contiguous,
// makes both the strided LDS.128 and the staging STS conflict-free.
__device__ __forceinline__ unsigned swz(unsigned idx) {
    return idx ^ (((idx >> 5) & 7u) << 2);
}

__global__ __launch_bounds__(TPB)
void tlc_kernel(const int* __restrict__ tok,
                const float* __restrict__ table,
                float* __restrict__ out)
{
    const int lane = threadIdx.x & 31;
    const int wid  = threadIdx.x >> 5;
    const int row  = blockIdx.x * RPC + wid;
    const int* t   = tok + (size_t)row * SEQ;

    __shared__ unsigned sTok[RPC][SEQ / 4];     // 4 KB per warp, byte-packed row
    unsigned* S = sTok[wid];

    // ---- stage whole row: coalesced int4 loads, pack to bytes, swizzled STS
    const int4* g = reinterpret_cast<const int4*>(t);
    #pragma unroll 4
    for (int i = 0; i < 32; i++) {
        int4 v = g[i * 32 + lane];              // warp covers 512B contiguous
        unsigned lo = prmt(v.x, v.y, 0x0040);
        unsigned hi = prmt(v.z, v.w, 0x4000);
        S[swz(i * 32 + lane)] = prmt(lo, hi, 0x7610);
    }
    __syncwarp();

    // query tag from last token (byte3 of word 1023); t[1] = byte1 of word 0
    const int qtag = min(max((int)(S[swz(1023)] >> 24) - 46, 0), 2);

    int rtag = -1;                 // running tag; -1 = nothing seen yet in thread
    unsigned mL = 0, mC = 0;
    const int wbase = lane * 32;   // my 32 packed words = 128 contiguous tokens

    #pragma unroll
    for (int b = 0; b < 8; b++) {
        unsigned P[4];
        *reinterpret_cast<uint4*>(P) =
            *reinterpret_cast<const uint4*>(&S[swz(wbase + 4 * b)]);
        const int nidx = wbase + 4 * b + 4;
        const unsigned nfw = (nidx < SEQ / 4) ? S[swz(nidx)] : 0u;  // row-end sentinel
        unsigned N[4];
        N[0] = prmt(P[0], P[1], 0x4321);
        N[1] = prmt(P[1], P[2], 0x4321);
        N[2] = prmt(P[2], P[3], 0x4321);
        N[3] = prmt(P[3], nfw,  0x4321);

        // ---- SWAR detection (verbatim from validated kernel)
        unsigned tagpos = 0, candpos = 0;
        #pragma unroll
        for (int w = 0; w < 4; w++) {
            unsigned p = P[w], n = N[w];
            unsigned d1 = p + 0x52525252u;              // tag: (c-46) <u 3
            unsigned d2 = d1 - 0x03030303u;
            unsigned tm = (d1 & ~d2) & 0x80808080u;
            unsigned r1 = p + 0x7D7D7D7Du;              // role: (c-3) <u 3
            unsigned r2 = r1 - 0x03030303u;
            unsigned rm = (r1 & ~r2) & 0x80808080u;
            unsigned c8  = (p << 3) & 0xF8F8F8F8u;
            unsigned c8r = c8 & ((rm >> 7) * 0xF8u);    // mask junk-byte borrows
            unsigned e1 = (n + 0x82828282u) - c8r;      // (n+2-8c) >= 0
            unsigned e2 = e1 - 0x08080808u;             // (n+2-8c) >= 8
            unsigned cm = (e1 & ~e2) & rm;
            tagpos  |= ((tm * 0x00204081u) >> 28) << (4 * w);
            candpos |= ((cm * 0x00204081u) >> 28) << (4 * w);
        }

        // ---- rare path: resolve each candidate's governing tag
        while (candpos) {
            int k = __ffs(candpos) - 1;
            candpos &= candpos - 1;
            unsigned nw = (k & 8) ? ((k & 4) ? N[3] : N[2])
                                  : ((k & 4) ? N[1] : N[0]);
            unsigned u  = (prmt(nw, 0u, (unsigned)(k & 3)) & 0xFFu) - 22u;
            unsigned bit = 1u << u;
            unsigned tb = tagpos & ((2u << k) - 1u);    // in-batch tags at pos <= k
            if (tb) {
                int j = 31 - __clz(tb);
                unsigned pw = (j & 8) ? ((j & 4) ? P[3] : P[2])
                                      : ((j & 4) ? P[1] : P[0]);
                int tv = (int)(prmt(pw, 0u, (unsigned)(j & 3)) & 0xFFu) - 46;
                if (tv == qtag) mL |= bit;
            } else if (rtag >= 0) {
                if (rtag == qtag) mL |= bit;            // governed by running tag
            } else {
                mC |= bit;                              // pending: carry from prior threads
            }
        }

        // ---- update running tag from this batch
        if (tagpos) {
            int j = 31 - __clz(tagpos);
            unsigned pw = (j & 8) ? ((j & 4) ? P[3] : P[2])
                                  : ((j & 4) ? P[1] : P[0]);
            rtag = (int)(prmt(pw, 0u, (unsigned)(j & 3)) & 0xFFu) - 46;
        }
    }

    // ---- warp inclusive scan of rtag: combine(a,b) = (b>=0 ? b : a)
    int inc = rtag;
    #pragma unroll
    for (int off = 1; off < 32; off <<= 1) {
        int p = __shfl_up_sync(0xffffffffu, inc, off);
        if (lane >= off && inc < 0) inc = p;
    }
    int excl = __shfl_up_sync(0xffffffffu, inc, 1);
    if (lane == 0) excl = -1;                           // row start: no tag

    unsigned m = mL | ((excl == qtag) ? mC : 0u);
    m = __reduce_or_sync(0xffffffffu, m);

    // ---- epilogue: lane 0 of each warp finishes its row
    if (lane == 0) {
        unsigned mA  =  m        & 0xffu;
        unsigned mB  = (m >> 8)  & 0xffu;
        unsigned mCm = (m >> 16) & 0xffu;
        const int a = mA  ? (__ffs(mA)  - 1) : 0;
        const int b = mB  ? (__ffs(mB)  - 1) : 0;
        const int c = mCm ? (__ffs(mCm) - 1) : 0;

        const int task = min(max((int)((S[0] >> 8) & 0xFFu) - 49, 0), 3);

        float o[8];
        if (task == 3) {
            const float* tp = table + (((a * 8 + b) * 8 + c) * 8);
            #pragma unroll
            for (int k = 0; k < 8; k++) o[k] = __ldg(&tp[k]);
        } else {
            int idx;
            if (task == 0)      idx = a;
            else if (task == 1) idx = (a + 2 * b + 3 * c) & 7;
            else                idx = (a * (b + 1) + c * ((a ^ b) + 1)) & 7;
            #pragma unroll
            for (int k = 0; k < 8; k++) o[k] = (k == idx) ? 12.0f : 0.0f;
        }

        float4* o4 = reinterpret_cast<float4*>(out + (size_t)row * 8);
        o4[0] = make_float4(o[0], o[1], o[2], o[3]);
        o4[1] = make_float4(o[4], o[5], o[6], o[7]);
    }
}

extern "C" void kernel_launch(void* const* d_in, const int* in_sizes, int n_in,
                              void* d_out, int out_size)
{
    const int* tok     = (const int*)d_in[0];     // token_ids [B, 4096] int32
    const float* table = (const float*)d_in[1];   // lookup_table [8,8,8,8] f32
    float* out         = (float*)d_out;           // [B, 8] f32

    const int B = in_sizes[0] / SEQ;
    tlc_kernel<<<B / RPC, TPB>>>(tok, table, out);
}

// round 9
// speedup vs baseline: 1.0020x; 1.0020x over previous
#include <cuda_runtime.h>

#define SEQ 4096
#define TPB 128               // one row per CTA, 32 tokens per thread
#define NW (TPB / 32)

__device__ __forceinline__ unsigned prmt(unsigned a, unsigned b, unsigned sel) {
    unsigned r;
    asm("prmt.b32 %0, %1, %2, %3;" : "=r"(r) : "r"(a), "r"(b), "r"(sel));
    return r;
}

// word-index swizzle: XOR bits[4:2] ^= bits[7:5]. Keeps 16B groups intact;
// staging STS (stride-1 + const XOR) and processing LDS.128 (stride-8 words)
// both come out conflict-free.
__device__ __forceinline__ unsigned swz(unsigned idx) {
    return idx ^ (((idx >> 5) & 7u) << 2);
}

// SWAR detect + resolve for one 4-word batch (16 tokens). Verbatim logic from
// the validated kernel; rtag = thread-running tag carried across batches.
__device__ __forceinline__ void batch16(const unsigned P[4], unsigned nfw, int qtag,
                                        int& rtag, unsigned& mL, unsigned& mC)
{
    unsigned N[4];
    N[0] = prmt(P[0], P[1], 0x4321);
    N[1] = prmt(P[1], P[2], 0x4321);
    N[2] = prmt(P[2], P[3], 0x4321);
    N[3] = prmt(P[3], nfw,  0x4321);

    unsigned tagpos = 0, candpos = 0;
    #pragma unroll
    for (int w = 0; w < 4; w++) {
        unsigned p = P[w], n = N[w];
        unsigned d1 = p + 0x52525252u;              // tag: (c-46) <u 3
        unsigned d2 = d1 - 0x03030303u;
        unsigned tm = (d1 & ~d2) & 0x80808080u;
        unsigned r1 = p + 0x7D7D7D7Du;              // role: (c-3) <u 3
        unsigned r2 = r1 - 0x03030303u;
        unsigned rm = (r1 & ~r2) & 0x80808080u;
        unsigned c8  = (p << 3) & 0xF8F8F8F8u;
        unsigned c8r = c8 & ((rm >> 7) * 0xF8u);    // mask junk-byte borrows
        unsigned e1 = (n + 0x82828282u) - c8r;      // (n+2-8c) >= 0
        unsigned e2 = e1 - 0x08080808u;             // (n+2-8c) >= 8
        unsigned cm = (e1 & ~e2) & rm;
        tagpos  |= ((tm * 0x00204081u) >> 28) << (4 * w);
        candpos |= ((cm * 0x00204081u) >> 28) << (4 * w);
    }

    while (candpos) {
        int k = __ffs(candpos) - 1;
        candpos &= candpos - 1;
        unsigned nw = (k & 8) ? ((k & 4) ? N[3] : N[2])
                              : ((k & 4) ? N[1] : N[0]);
        unsigned u  = (prmt(nw, 0u, (unsigned)(k & 3)) & 0xFFu) - 22u;  // bit 0..23
        unsigned bit = 1u << u;
        unsigned tb = tagpos & ((2u << k) - 1u);    // in-batch tags at pos <= k
        if (tb) {
            int j = 31 - __clz(tb);
            unsigned pw = (j & 8) ? ((j & 4) ? P[3] : P[2])
                                  : ((j & 4) ? P[1] : P[0]);
            int tv = (int)(prmt(pw, 0u, (unsigned)(j & 3)) & 0xFFu) - 46;
            if (tv == qtag) mL |= bit;
        } else if (rtag >= 0) {
            if (rtag == qtag) mL |= bit;            // governed by running tag
        } else {
            mC |= bit;                              // pending: carry from earlier threads
        }
    }

    if (tagpos) {
        int j = 31 - __clz(tagpos);
        unsigned pw = (j & 8) ? ((j & 4) ? P[3] : P[2])
                              : ((j & 4) ? P[1] : P[0]);
        rtag = (int)(prmt(pw, 0u, (unsigned)(j & 3)) & 0xFFu) - 46;
    }
}

__global__ __launch_bounds__(TPB)
void tlc_kernel(const int* __restrict__ tok,
                const float* __restrict__ table,
                float* __restrict__ out)
{
    const int row  = blockIdx.x;
    const int* t   = tok + (size_t)row * SEQ;
    const int tid  = threadIdx.x;
    const int lane = tid & 31;
    const int wid  = tid >> 5;

    __shared__ unsigned sTok[SEQ / 4];              // byte-packed row, 4 KB
    __shared__ unsigned sM[NW], sP[NW];
    __shared__ int      sL[NW];

    // ---- stage whole row: 8 independent coalesced int4 loads per thread
    const int4* g = reinterpret_cast<const int4*>(t);
    #pragma unroll
    for (int i = 0; i < 8; i++) {
        int4 v = g[i * TPB + tid];
        unsigned lo = prmt(v.x, v.y, 0x0040);
        unsigned hi = prmt(v.z, v.w, 0x4000);
        sTok[swz(i * TPB + tid)] = prmt(lo, hi, 0x7610);
    }
    __syncthreads();

    const int qtag = min(max((int)(sTok[swz(SEQ / 4 - 1)] >> 24) - 46, 0), 2);
    const int wbase = tid * 8;                      // my 8 words = 32 tokens

    int rtag = -1;
    unsigned mL = 0, mC = 0;

    // batch 0: words 0..3; its boundary word is word 4 (loaded for batch 1)
    unsigned P0[4], P1[4];
    *reinterpret_cast<uint4*>(P0) = *reinterpret_cast<const uint4*>(&sTok[swz(wbase)]);
    *reinterpret_cast<uint4*>(P1) = *reinterpret_cast<const uint4*>(&sTok[swz(wbase + 4)]);
    batch16(P0, P1[0], qtag, rtag, mL, mC);

    // batch 1: words 4..7; boundary = next thread's first word (0 sentinel at row end)
    const unsigned nfw = (tid == TPB - 1) ? 0u : sTok[swz(wbase + 8)];
    batch16(P1, nfw, qtag, rtag, mL, mC);

    // ---- warp inclusive scan of rtag: combine(a,b) = (b>=0 ? b : a)
    int inc = rtag;
    #pragma unroll
    for (int off = 1; off < 32; off <<= 1) {
        int p = __shfl_up_sync(0xffffffffu, inc, off);
        if (lane >= off && inc < 0) inc = p;
    }
    int excl = __shfl_up_sync(0xffffffffu, inc, 1);
    if (lane == 0) excl = -1;

    unsigned m    = mL | ((excl == qtag) ? mC : 0u);
    unsigned pend = (excl < 0) ? mC : 0u;

    m    = __reduce_or_sync(0xffffffffu, m);
    pend = __reduce_or_sync(0xffffffffu, pend);
    const int wlast = __shfl_sync(0xffffffffu, inc, 31);

    if (lane == 0) { sM[wid] = m; sP[wid] = pend; sL[wid] = wlast; }
    __syncthreads();

    // ---- cross-warp resolve + epilogue (4 threads of warp 0)
    if (tid < NW) {
        unsigned mm = sM[tid], pp = sP[tid];
        int c2 = sL[tid];
        #pragma unroll
        for (int off = 1; off < NW; off <<= 1) {
            int p = __shfl_up_sync(0xfu, c2, off);
            if (tid >= off && c2 < 0) c2 = p;
        }
        int ex = __shfl_up_sync(0xfu, c2, 1);
        if (tid == 0) ex = -1;
        unsigned res = mm | ((ex == qtag) ? pp : 0u);
        res = __reduce_or_sync(0xfu, res);

        if (tid == 0) {
            unsigned mA  =  res        & 0xffu;
            unsigned mB  = (res >> 8)  & 0xffu;
            unsigned mCm = (res >> 16) & 0xffu;
            const int a = mA  ? (__ffs(mA)  - 1) : 0;
            const int b = mB  ? (__ffs(mB)  - 1) : 0;
            const int c = mCm ? (__ffs(mCm) - 1) : 0;

            const int task = min(max((int)((sTok[0] >> 8) & 0xFFu) - 49, 0), 3);

            float o[8];
            if (task == 3) {
                const float* tp = table + (((a * 8 + b) * 8 + c) * 8);
                #pragma unroll
                for (int k = 0; k < 8; k++) o[k] = __ldg(&tp[k]);
            } else {
                int idx;
                if (task == 0)      idx = a;
                else if (task == 1) idx = (a + 2 * b + 3 * c) & 7;
                else                idx = (a * (b + 1) + c * ((a ^ b) + 1)) & 7;
                #pragma unroll
                for (int k = 0; k < 8; k++) o[k] = (k == idx) ? 12.0f : 0.0f;
            }

            float4* o4 = reinterpret_cast<float4*>(out + (size_t)row * 8);
            o4[0] = make_float4(o[0], o[1], o[2], o[3]);
            o4[1] = make_float4(o[4], o[5], o[6], o[7]);
        }
    }
}

extern "C" void kernel_launch(void* const* d_in, const int* in_sizes, int n_in,
                              void* d_out, int out_size)
{
    const int* tok     = (const int*)d_in[0];     // token_ids [B, 4096] int32
    const float* table = (const float*)d_in[1];   // lookup_table [8,8,8,8] f32
    float* out         = (float*)d_out;           // [B, 8] f32

    const int B = in_sizes[0] / SEQ;
    tlc_kernel<<<B, TPB>>>(tok, table, out);
}